// round 5
// baseline (speedup 1.0000x reference)
#include <cuda_runtime.h>
#include <math.h>

#define NN 4096
#define EE 8192
#define DD 64
#define LL 16
#define HH 768
#define FF 3072
#define VV 32000

// ---------------- scratch (static device globals; no allocation) ----------------
__device__ float g_h[NN * DD];
__device__ float g_agg[NN * DD];
__device__ float g_no[NN * DD];
__device__ float g_x[(size_t)EE * HH];
__device__ float g_xn[(size_t)EE * HH];
__device__ float g_hid[(size_t)EE * FF];
__device__ float g_hidden[(size_t)EE * HH];
__device__ float g_proj[(size_t)EE * DD];

__device__ __forceinline__ float gelu_tanh(float x) {
    float x3 = x * x * x;
    float t = tanhf(0.7978845608028654f * (x + 0.044715f * x3));
    return 0.5f * x * (1.0f + t);
}

// ---------------- zero the aggregation buffer ----------------
__global__ void k_zero() {
    int i = blockIdx.x * 256 + threadIdx.x;
    if (i < NN * DD) g_agg[i] = 0.0f;
}

// ---------------- h = relu(emb[x_tokens] @ W1 + b1)  [N,64] ----------------
__global__ void k_node_h(const int* __restrict__ xtok, const float* __restrict__ emb,
                         const float* __restrict__ W1, const float* __restrict__ b1) {
    __shared__ float s[LL * DD];  // gathered token embeddings, 1024 floats
    int n = blockIdx.x, tid = threadIdx.x;
#pragma unroll
    for (int j = 0; j < LL; j++) {
        int tok = xtok[n * LL + j];
        s[j * DD + tid] = emb[(size_t)tok * DD + tid];
    }
    __syncthreads();
    float acc = b1[tid];
#pragma unroll 8
    for (int k = 0; k < LL * DD; k += 4) {
        float4 sv = *(const float4*)&s[k];
        acc += sv.x * W1[(k + 0) * DD + tid];
        acc += sv.y * W1[(k + 1) * DD + tid];
        acc += sv.z * W1[(k + 2) * DD + tid];
        acc += sv.w * W1[(k + 3) * DD + tid];
    }
    g_h[n * DD + tid] = fmaxf(acc, 0.0f);
}

// ---------------- msg = emb[edge_tokens]@We + h[src]; atomic scatter into agg[dst] ----------------
__global__ void k_edge_msg(const int* __restrict__ etok, const float* __restrict__ emb,
                           const float* __restrict__ We, const int* __restrict__ eidx) {
    __shared__ float s[LL * DD];
    int e = blockIdx.x, tid = threadIdx.x;
#pragma unroll
    for (int j = 0; j < LL; j++) {
        int tok = etok[e * LL + j];
        s[j * DD + tid] = emb[(size_t)tok * DD + tid];
    }
    __syncthreads();
    float acc = 0.0f;
#pragma unroll 8
    for (int k = 0; k < LL * DD; k += 4) {
        float4 sv = *(const float4*)&s[k];
        acc += sv.x * We[(k + 0) * DD + tid];
        acc += sv.y * We[(k + 1) * DD + tid];
        acc += sv.z * We[(k + 2) * DD + tid];
        acc += sv.w * We[(k + 3) * DD + tid];
    }
    int src = eidx[e], dst = eidx[EE + e];
    float m = acc + g_h[src * DD + tid];
    atomicAdd(&g_agg[dst * DD + tid], m);
}

// ---------------- node_out = relu((h+agg) @ W2 + b2) ----------------
__global__ void k_node_out(const float* __restrict__ W2, const float* __restrict__ b2) {
    __shared__ float s[DD];
    int n = blockIdx.x, tid = threadIdx.x;
    s[tid] = g_h[n * DD + tid] + g_agg[n * DD + tid];
    __syncthreads();
    float acc = b2[tid];
#pragma unroll
    for (int k = 0; k < DD; k += 4) {
        float4 sv = *(const float4*)&s[k];
        acc += sv.x * W2[(k + 0) * DD + tid];
        acc += sv.y * W2[(k + 1) * DD + tid];
        acc += sv.z * W2[(k + 2) * DD + tid];
        acc += sv.w * W2[(k + 3) * DD + tid];
    }
    g_no[n * DD + tid] = fmaxf(acc, 0.0f);
}

// ---------------- x = (node_out[src]+node_out[dst]) @ Wc1 + bc1   [E,768] ----------------
// 8 edges per block, 256 threads, each thread 3 output columns
__global__ void k_edge_x(const int* __restrict__ eidx, const float* __restrict__ Wc1,
                         const float* __restrict__ bc1) {
    __shared__ float s[8][DD];
    int e0 = blockIdx.x * 8, tid = threadIdx.x;
    for (int idx = tid; idx < 8 * DD; idx += 256) {
        int e = idx >> 6, k = idx & 63;
        int ge = e0 + e;
        int sN = eidx[ge], dN = eidx[EE + ge];
        s[e][k] = g_no[sN * DD + k] + g_no[dN * DD + k];
    }
    __syncthreads();
    for (int jj = 0; jj < 3; jj++) {
        int j = jj * 256 + tid;
        float acc[8];
        float bv = bc1[j];
#pragma unroll
        for (int e = 0; e < 8; e++) acc[e] = bv;
        for (int k = 0; k < DD; k += 4) {
            float w0 = Wc1[(k + 0) * HH + j];
            float w1 = Wc1[(k + 1) * HH + j];
            float w2 = Wc1[(k + 2) * HH + j];
            float w3 = Wc1[(k + 3) * HH + j];
#pragma unroll
            for (int e = 0; e < 8; e++) {
                float4 sv = *(const float4*)&s[e][k];
                acc[e] += sv.x * w0 + sv.y * w1 + sv.z * w2 + sv.w * w3;
            }
        }
#pragma unroll
        for (int e = 0; e < 8; e++) g_x[(size_t)(e0 + e) * HH + j] = acc[e];
    }
}

// ---------------- LayerNorm over H=768 ----------------
__global__ void k_ln(const float* __restrict__ lng, const float* __restrict__ lnb) {
    __shared__ float red[256];
    int row = blockIdx.x, tid = threadIdx.x;
    float v[3];
#pragma unroll
    for (int i = 0; i < 3; i++) v[i] = g_x[(size_t)row * HH + tid + i * 256];
    float sum = v[0] + v[1] + v[2];
    red[tid] = sum;
    __syncthreads();
    for (int s = 128; s > 0; s >>= 1) {
        if (tid < s) red[tid] += red[tid + s];
        __syncthreads();
    }
    float mu = red[0] / (float)HH;
    __syncthreads();
    float d2 = 0.0f;
#pragma unroll
    for (int i = 0; i < 3; i++) { float d = v[i] - mu; d2 += d * d; }
    red[tid] = d2;
    __syncthreads();
    for (int s = 128; s > 0; s >>= 1) {
        if (tid < s) red[tid] += red[tid + s];
        __syncthreads();
    }
    float inv = rsqrtf(red[0] / (float)HH + 1e-5f);
#pragma unroll
    for (int i = 0; i < 3; i++) {
        int j = tid + i * 256;
        g_xn[(size_t)row * HH + j] = (v[i] - mu) * inv * lng[j] + lnb[j];
    }
}

// ---------------- generic 128x128 tiled SGEMM, KT=16, 8x8 micro-tile ----------------
// EPI: 0=none, 1=gelu, 2=+residual R.  TB: B is [N,K] row-major (use B^T).
template <int EPI, bool TB>
__global__ __launch_bounds__(256) void k_gemm(const float* __restrict__ A,
                                              const float* __restrict__ B,
                                              const float* __restrict__ bias,
                                              const float* __restrict__ R,
                                              float* __restrict__ C,
                                              int M, int Nn, int K) {
    __shared__ float As[16][128];
    __shared__ float Bs[16][128];
    int tid = threadIdx.x, tx = tid & 15, ty = tid >> 4;
    int n0 = blockIdx.x * 128, m0 = blockIdx.y * 128;
    float acc[8][8] = {};
    for (int kt = 0; kt < K; kt += 16) {
        for (int f = tid; f < 512; f += 256) {
            int m = f >> 2, kq = f & 3;
            float4 v = *(const float4*)&A[(size_t)(m0 + m) * K + kt + kq * 4];
            As[kq * 4 + 0][m] = v.x; As[kq * 4 + 1][m] = v.y;
            As[kq * 4 + 2][m] = v.z; As[kq * 4 + 3][m] = v.w;
        }
        if (!TB) {
            for (int f = tid; f < 512; f += 256) {
                int k = f >> 5, n4 = f & 31;
                *(float4*)&Bs[k][n4 * 4] =
                    *(const float4*)&B[(size_t)(kt + k) * Nn + n0 + n4 * 4];
            }
        } else {
            for (int f = tid; f < 512; f += 256) {
                int n = f >> 2, kq = f & 3;
                float4 v = *(const float4*)&B[(size_t)(n0 + n) * K + kt + kq * 4];
                Bs[kq * 4 + 0][n] = v.x; Bs[kq * 4 + 1][n] = v.y;
                Bs[kq * 4 + 2][n] = v.z; Bs[kq * 4 + 3][n] = v.w;
            }
        }
        __syncthreads();
#pragma unroll
        for (int k = 0; k < 16; k++) {
            float a[8], b[8];
            *(float4*)&a[0] = *(const float4*)&As[k][ty * 8];
            *(float4*)&a[4] = *(const float4*)&As[k][ty * 8 + 4];
            *(float4*)&b[0] = *(const float4*)&Bs[k][tx * 8];
            *(float4*)&b[4] = *(const float4*)&Bs[k][tx * 8 + 4];
#pragma unroll
            for (int i = 0; i < 8; i++)
#pragma unroll
                for (int j = 0; j < 8; j++) acc[i][j] += a[i] * b[j];
        }
        __syncthreads();
    }
#pragma unroll
    for (int i = 0; i < 8; i++) {
        int row = m0 + ty * 8 + i;
#pragma unroll
        for (int j = 0; j < 8; j++) {
            int col = n0 + tx * 8 + j;
            float v = acc[i][j];
            if (bias) v += bias[col];
            if (EPI == 1) v = gelu_tanh(v);
            if (EPI == 2) v += R[(size_t)row * Nn + col];
            C[(size_t)row * Nn + col] = v;
        }
    }
}

// ---------------- proj = hidden @ Wc2 + bc2   [E,64] ----------------
// 16 edges/block, 256 threads = 64 d-cols x 4 edge-groups
__global__ void k_proj(const float* __restrict__ Wc2, const float* __restrict__ bc2) {
    __shared__ float s[16][HH];
    int e0 = blockIdx.x * 16, tid = threadIdx.x;
    int d = tid & 63, eg = tid >> 6;
    for (int idx = tid; idx < 16 * HH / 4; idx += 256) {
        int e = idx / (HH / 4), q = idx % (HH / 4);
        *(float4*)&s[e][q * 4] = *(const float4*)&g_hidden[(size_t)(e0 + e) * HH + q * 4];
    }
    __syncthreads();
    float acc[4];
    float bv = bc2[d];
#pragma unroll
    for (int i = 0; i < 4; i++) acc[i] = bv;
    for (int k = 0; k < HH; k += 4) {
        float w0 = Wc2[(k + 0) * DD + d];
        float w1 = Wc2[(k + 1) * DD + d];
        float w2 = Wc2[(k + 2) * DD + d];
        float w3 = Wc2[(k + 3) * DD + d];
#pragma unroll
        for (int i = 0; i < 4; i++) {
            int e = eg * 4 + i;
            float4 sv = *(const float4*)&s[e][k];
            acc[i] += sv.x * w0 + sv.y * w1 + sv.z * w2 + sv.w * w3;
        }
    }
#pragma unroll
    for (int i = 0; i < 4; i++) g_proj[(size_t)(e0 + eg * 4 + i) * DD + d] = acc[i];
}

// ---------------- in-place softmax over V (row resident in dynamic smem) ----------------
__global__ void k_softmax(float* __restrict__ out) {
    extern __shared__ float rowbuf[];
    __shared__ float red[256];
    size_t base = (size_t)blockIdx.x * VV;
    int tid = threadIdx.x;
    float m = -3.4e38f;
    for (int v = tid; v < VV; v += 256) {
        float x = out[base + v];
        rowbuf[v] = x;
        m = fmaxf(m, x);
    }
    red[tid] = m;
    __syncthreads();
    for (int s = 128; s > 0; s >>= 1) {
        if (tid < s) red[tid] = fmaxf(red[tid], red[tid + s]);
        __syncthreads();
    }
    float M = red[0];
    __syncthreads();
    float ssum = 0.0f;
    for (int v = tid; v < VV; v += 256) {
        float e = expf(rowbuf[v] - M);
        rowbuf[v] = e;
        ssum += e;
    }
    red[tid] = ssum;
    __syncthreads();
    for (int s = 128; s > 0; s >>= 1) {
        if (tid < s) red[tid] += red[tid + s];
        __syncthreads();
    }
    float inv = 1.0f / red[0];
    for (int v = tid; v < VV; v += 256) out[base + v] = rowbuf[v] * inv;
}

// ---------------- labels = (float)edge_tokens ----------------
__global__ void k_labels(const int* __restrict__ etok, float* __restrict__ out) {
    int i = blockIdx.x * 256 + threadIdx.x;
    if (i < EE * LL) out[i] = (float)etok[i];
}

// ---------------- launch ----------------
extern "C" void kernel_launch(void* const* d_in, const int* in_sizes, int n_in,
                              void* d_out, int out_size) {
    const int*   xtok = (const int*)d_in[0];
    const int*   etok = (const int*)d_in[1];
    const int*   eidx = (const int*)d_in[2];
    const float* emb  = (const float*)d_in[3];
    const float* W1   = (const float*)d_in[4];
    const float* b1   = (const float*)d_in[5];
    const float* We   = (const float*)d_in[6];
    const float* W2   = (const float*)d_in[7];
    const float* b2   = (const float*)d_in[8];
    const float* Wc1  = (const float*)d_in[9];
    const float* bc1  = (const float*)d_in[10];
    const float* lng  = (const float*)d_in[11];
    const float* lnb  = (const float*)d_in[12];
    const float* Wt1  = (const float*)d_in[13];
    const float* bt1  = (const float*)d_in[14];
    const float* Wt2  = (const float*)d_in[15];
    const float* bt2  = (const float*)d_in[16];
    const float* Wc2  = (const float*)d_in[17];
    const float* bc2  = (const float*)d_in[18];

    float* out = (float*)d_out;
    long long off = (long long)out_size - (long long)EE * VV;
    float* probs = out + (off > 0 ? off : 0);

    float *p_xn, *p_hid, *p_x, *p_hidden, *p_proj;
    cudaGetSymbolAddress((void**)&p_xn, g_xn);
    cudaGetSymbolAddress((void**)&p_hid, g_hid);
    cudaGetSymbolAddress((void**)&p_x, g_x);
    cudaGetSymbolAddress((void**)&p_hidden, g_hidden);
    cudaGetSymbolAddress((void**)&p_proj, g_proj);

    k_zero<<<(NN * DD + 255) / 256, 256>>>();
    k_node_h<<<NN, 64>>>(xtok, emb, W1, b1);
    k_edge_msg<<<EE, 64>>>(etok, emb, We, eidx);
    k_node_out<<<NN, 64>>>(W2, b2);
    k_edge_x<<<EE / 8, 256>>>(eidx, Wc1, bc1);
    k_ln<<<EE, 256>>>(lng, lnb);
    // FFN up: gelu(xn @ Wt1 + bt1)
    k_gemm<1, false><<<dim3(FF / 128, EE / 128), 256>>>(p_xn, Wt1, bt1, nullptr, p_hid, EE, FF, HH);
    // FFN down + residual: hid @ Wt2 + bt2 + x
    k_gemm<2, false><<<dim3(HH / 128, EE / 128), 256>>>(p_hid, Wt2, bt2, p_x, p_hidden, EE, HH, FF);
    k_proj<<<EE / 16, 256>>>(Wc2, bc2);
    // LM head: proj @ emb^T -> logits staged directly in d_out probs region
    k_gemm<0, true><<<dim3(VV / 128, EE / 128), 256>>>(p_proj, emb, nullptr, nullptr, probs, EE, VV, DD);
    if (off > 0) k_labels<<<(EE * LL + 255) / 256, 256>>>(etok, out);
    cudaFuncSetAttribute((const void*)k_softmax,
                         cudaFuncAttributeMaxDynamicSharedMemorySize, VV * 4);
    k_softmax<<<EE, 256, VV * 4>>>(probs);
}

// round 8
// speedup vs baseline: 4.3125x; 4.3125x over previous
#include <cuda_runtime.h>
#include <cuda_bf16.h>
#include <math.h>
#include <cstdint>

#define NN 4096
#define EE 8192
#define DD 64
#define LL 16
#define HH 768
#define FF 3072
#define VV 32000

// ---------------- scratch (static device globals; no allocation) ----------------
__device__ float g_h[NN * DD];
__device__ float g_agg[NN * DD];
__device__ float g_no[NN * DD];
__device__ float g_x[(size_t)EE * HH];          // pre-LN activations (residual)
__device__ float g_hidden[(size_t)EE * HH];     // transformer output fp32
__device__ float g_rowsum[EE];                  // softmax denominators
__device__ __nv_bfloat16 g_xnb[(size_t)EE * HH];    // LN output bf16
__device__ __nv_bfloat16 g_hidb[(size_t)EE * FF];   // gelu output bf16
__device__ __nv_bfloat16 g_projb[(size_t)EE * DD];  // proj bf16
__device__ __nv_bfloat16 g_wt1t[(size_t)FF * HH];   // Wt1^T bf16 [3072,768]
__device__ __nv_bfloat16 g_wt2t[(size_t)HH * FF];   // Wt2^T bf16 [768,3072]
__device__ __nv_bfloat16 g_embb[(size_t)VV * DD];   // emb bf16 [32000,64]

__device__ __forceinline__ float gelu_tanh(float x) {
    float x3 = x * x * x;
    float t = tanhf(0.7978845608028654f * (x + 0.044715f * x3));
    return 0.5f * x * (1.0f + t);
}

__device__ __forceinline__ uint32_t smem_u32(const void* p) {
    uint32_t a;
    asm("{ .reg .u64 t; cvta.to.shared.u64 t, %1; cvt.u32.u64 %0, t; }" : "=r"(a) : "l"(p));
    return a;
}

// ================= mma.sync bf16 GEMM: C[M,Nn] = A[M,K] @ B[Nn,K]^T =================
// BM=BN=128, BK=32. 256 threads = 8 warps (2x4), warp tile 64x32.
// EPI: 1 = gelu(acc+bias) -> bf16 C
//      2 = acc+bias+R -> fp32 C
//      3 = rowsum[row] += sum(exp(acc))      (no C write)
//      4 = C = exp(acc) * (1/rowsum[row]) -> fp32
#define SMS 80  // smem row stride in bytes (32 bf16 = 64B data + 16B pad)

template <int EPI>
__global__ __launch_bounds__(256) void k_mma_gemm(
    const __nv_bfloat16* __restrict__ A, const __nv_bfloat16* __restrict__ B,
    const float* __restrict__ bias, const float* __restrict__ R,
    void* __restrict__ Cout, float* __restrict__ rowsum,
    int M, int Nn, int K)
{
    __shared__ __align__(16) char smA[128 * SMS];
    __shared__ __align__(16) char smB[128 * SMS];
    __shared__ float srow[128];

    const int t = threadIdx.x;
    const int l = t & 31, w = t >> 5;
    const int wm = w & 1, wn = w >> 1;        // 2 x 4 warp grid
    const int m0 = blockIdx.y * 128, n0 = blockIdx.x * 128;

    if (EPI == 3 && t < 128) srow[t] = 0.0f;

    // global->reg->smem staging indices (2 x 16B chunks per thread per tile)
    int rowL[2], c4L[2];
#pragma unroll
    for (int i = 0; i < 2; i++) {
        int chunk = t * 2 + i;
        rowL[i] = chunk >> 2;
        c4L[i] = chunk & 3;
    }
    uint4 va[2], vb[2];

    const uint32_t uA = smem_u32(smA), uB = smem_u32(smB);
    // ldmatrix base addresses
    const int rA = wm * 64 + (l & 7) + ((l >> 3) & 1) * 8;
    const uint32_t aBase = uA + (uint32_t)rA * SMS + (uint32_t)(l >> 4) * 16;
    const int lB = l & 15;
    const uint32_t bBase = uB + (uint32_t)(wn * 32 + (lB & 7)) * SMS + (uint32_t)(lB >> 3) * 16;

    float acc[4][4][4] = {};

    const int nk = K >> 5;
    // prologue load of tile 0
#pragma unroll
    for (int i = 0; i < 2; i++) {
        va[i] = *(const uint4*)(A + (size_t)(m0 + rowL[i]) * K + c4L[i] * 8);
        vb[i] = *(const uint4*)(B + (size_t)(n0 + rowL[i]) * K + c4L[i] * 8);
    }
#pragma unroll
    for (int i = 0; i < 2; i++) {
        *(uint4*)(smA + rowL[i] * SMS + c4L[i] * 16) = va[i];
        *(uint4*)(smB + rowL[i] * SMS + c4L[i] * 16) = vb[i];
    }
    __syncthreads();

    for (int it = 0; it < nk; it++) {
        if (it + 1 < nk) {
            int kt = (it + 1) * 32;
#pragma unroll
            for (int i = 0; i < 2; i++) {
                va[i] = *(const uint4*)(A + (size_t)(m0 + rowL[i]) * K + kt + c4L[i] * 8);
                vb[i] = *(const uint4*)(B + (size_t)(n0 + rowL[i]) * K + kt + c4L[i] * 8);
            }
        }
#pragma unroll
        for (int ks = 0; ks < 2; ks++) {
            uint32_t a[4][4], b[4][2];
#pragma unroll
            for (int i = 0; i < 4; i++) {
                uint32_t ad = aBase + (uint32_t)(i * 16) * SMS + (uint32_t)(ks * 32);
                asm volatile("ldmatrix.sync.aligned.m8n8.x4.shared.b16 {%0,%1,%2,%3}, [%4];"
                             : "=r"(a[i][0]), "=r"(a[i][1]), "=r"(a[i][2]), "=r"(a[i][3])
                             : "r"(ad));
            }
#pragma unroll
            for (int j = 0; j < 4; j++) {
                uint32_t bd = bBase + (uint32_t)(j * 8) * SMS + (uint32_t)(ks * 32);
                asm volatile("ldmatrix.sync.aligned.m8n8.x2.shared.b16 {%0,%1}, [%2];"
                             : "=r"(b[j][0]), "=r"(b[j][1]) : "r"(bd));
            }
#pragma unroll
            for (int i = 0; i < 4; i++)
#pragma unroll
                for (int j = 0; j < 4; j++) {
                    asm volatile(
                        "mma.sync.aligned.m16n8k16.row.col.f32.bf16.bf16.f32 "
                        "{%0,%1,%2,%3}, {%4,%5,%6,%7}, {%8,%9}, {%0,%1,%2,%3};"
                        : "+f"(acc[i][j][0]), "+f"(acc[i][j][1]),
                          "+f"(acc[i][j][2]), "+f"(acc[i][j][3])
                        : "r"(a[i][0]), "r"(a[i][1]), "r"(a[i][2]), "r"(a[i][3]),
                          "r"(b[j][0]), "r"(b[j][1]));
                }
        }
        __syncthreads();
        if (it + 1 < nk) {
#pragma unroll
            for (int i = 0; i < 2; i++) {
                *(uint4*)(smA + rowL[i] * SMS + c4L[i] * 16) = va[i];
                *(uint4*)(smB + rowL[i] * SMS + c4L[i] * 16) = vb[i];
            }
            __syncthreads();
        }
    }

    // ---------------- epilogue ----------------
    const int mw = m0 + wm * 64;          // warp m base (global)
    const int lrbase = wm * 64;           // warp m base (block-local)
#pragma unroll
    for (int i = 0; i < 4; i++) {
        int rlo = mw + i * 16 + (l >> 2);
        int rhi = rlo + 8;
        if (EPI == 3) {
            float slo = 0.0f, shi = 0.0f;
#pragma unroll
            for (int j = 0; j < 4; j++) {
                slo += __expf(acc[i][j][0]) + __expf(acc[i][j][1]);
                shi += __expf(acc[i][j][2]) + __expf(acc[i][j][3]);
            }
            slo += __shfl_xor_sync(0xFFFFFFFF, slo, 1);
            slo += __shfl_xor_sync(0xFFFFFFFF, slo, 2);
            shi += __shfl_xor_sync(0xFFFFFFFF, shi, 1);
            shi += __shfl_xor_sync(0xFFFFFFFF, shi, 2);
            if ((l & 3) == 0) {
                atomicAdd(&srow[lrbase + i * 16 + (l >> 2)], slo);
                atomicAdd(&srow[lrbase + i * 16 + (l >> 2) + 8], shi);
            }
        } else {
            float invlo = 0.0f, invhi = 0.0f;
            if (EPI == 4) { invlo = 1.0f / rowsum[rlo]; invhi = 1.0f / rowsum[rhi]; }
#pragma unroll
            for (int j = 0; j < 4; j++) {
                int col = n0 + wn * 32 + j * 8 + (l & 3) * 2;
                if (EPI == 1) {
                    float b0 = bias[col], b1 = bias[col + 1];
                    __nv_bfloat162 plo, phi;
                    plo.x = __float2bfloat16(gelu_tanh(acc[i][j][0] + b0));
                    plo.y = __float2bfloat16(gelu_tanh(acc[i][j][1] + b1));
                    phi.x = __float2bfloat16(gelu_tanh(acc[i][j][2] + b0));
                    phi.y = __float2bfloat16(gelu_tanh(acc[i][j][3] + b1));
                    *(__nv_bfloat162*)((__nv_bfloat16*)Cout + (size_t)rlo * Nn + col) = plo;
                    *(__nv_bfloat162*)((__nv_bfloat16*)Cout + (size_t)rhi * Nn + col) = phi;
                } else if (EPI == 2) {
                    float b0 = bias[col], b1 = bias[col + 1];
                    float2 plo, phi;
                    const float* Rlo = R + (size_t)rlo * Nn + col;
                    const float* Rhi = R + (size_t)rhi * Nn + col;
                    plo.x = acc[i][j][0] + b0 + Rlo[0];
                    plo.y = acc[i][j][1] + b1 + Rlo[1];
                    phi.x = acc[i][j][2] + b0 + Rhi[0];
                    phi.y = acc[i][j][3] + b1 + Rhi[1];
                    *(float2*)((float*)Cout + (size_t)rlo * Nn + col) = plo;
                    *(float2*)((float*)Cout + (size_t)rhi * Nn + col) = phi;
                } else {  // EPI == 4
                    float2 plo, phi;
                    plo.x = __expf(acc[i][j][0]) * invlo;
                    plo.y = __expf(acc[i][j][1]) * invlo;
                    phi.x = __expf(acc[i][j][2]) * invhi;
                    phi.y = __expf(acc[i][j][3]) * invhi;
                    *(float2*)((float*)Cout + (size_t)rlo * Nn + col) = plo;
                    *(float2*)((float*)Cout + (size_t)rhi * Nn + col) = phi;
                }
            }
        }
    }
    if (EPI == 3) {
        __syncthreads();
        if (t < 128) atomicAdd(&rowsum[m0 + t], srow[t]);
    }
}

// ---------------- conversion / transpose prolog ----------------
__global__ void k_transpose(const float* __restrict__ in, __nv_bfloat16* __restrict__ out,
                            int Rr, int Cc) {
    __shared__ float tbuf[32][33];
    int r0 = blockIdx.y * 32, c0 = blockIdx.x * 32;
    int x = threadIdx.x, y = threadIdx.y;
#pragma unroll
    for (int i = 0; i < 32; i += 8) tbuf[y + i][x] = in[(size_t)(r0 + y + i) * Cc + c0 + x];
    __syncthreads();
#pragma unroll
    for (int i = 0; i < 32; i += 8)
        out[(size_t)(c0 + y + i) * Rr + r0 + x] = __float2bfloat16(tbuf[x][y + i]);
}
__global__ void k_cvt(const float* __restrict__ in, __nv_bfloat16* __restrict__ out, int n) {
    int i = blockIdx.x * 256 + threadIdx.x;
    if (i < n) out[i] = __float2bfloat16(in[i]);
}
__global__ void k_zero() {
    int i = blockIdx.x * 256 + threadIdx.x;
    if (i < NN * DD) g_agg[i] = 0.0f;
    if (i < EE) g_rowsum[i] = 0.0f;
}

// ---------------- GNN front-end (fp32, small) ----------------
__global__ void k_node_h(const int* __restrict__ xtok, const float* __restrict__ emb,
                         const float* __restrict__ W1, const float* __restrict__ b1) {
    __shared__ float s[LL * DD];
    int n = blockIdx.x, tid = threadIdx.x;
#pragma unroll
    for (int j = 0; j < LL; j++) {
        int tok = xtok[n * LL + j];
        s[j * DD + tid] = emb[(size_t)tok * DD + tid];
    }
    __syncthreads();
    float acc = b1[tid];
#pragma unroll 8
    for (int k = 0; k < LL * DD; k += 4) {
        float4 sv = *(const float4*)&s[k];
        acc += sv.x * W1[(k + 0) * DD + tid];
        acc += sv.y * W1[(k + 1) * DD + tid];
        acc += sv.z * W1[(k + 2) * DD + tid];
        acc += sv.w * W1[(k + 3) * DD + tid];
    }
    g_h[n * DD + tid] = fmaxf(acc, 0.0f);
}

__global__ void k_edge_msg(const int* __restrict__ etok, const float* __restrict__ emb,
                           const float* __restrict__ We, const int* __restrict__ eidx) {
    __shared__ float s[LL * DD];
    int e = blockIdx.x, tid = threadIdx.x;
#pragma unroll
    for (int j = 0; j < LL; j++) {
        int tok = etok[e * LL + j];
        s[j * DD + tid] = emb[(size_t)tok * DD + tid];
    }
    __syncthreads();
    float acc = 0.0f;
#pragma unroll 8
    for (int k = 0; k < LL * DD; k += 4) {
        float4 sv = *(const float4*)&s[k];
        acc += sv.x * We[(k + 0) * DD + tid];
        acc += sv.y * We[(k + 1) * DD + tid];
        acc += sv.z * We[(k + 2) * DD + tid];
        acc += sv.w * We[(k + 3) * DD + tid];
    }
    int src = eidx[e], dst = eidx[EE + e];
    float m = acc + g_h[src * DD + tid];
    atomicAdd(&g_agg[dst * DD + tid], m);
}

__global__ void k_node_out(const float* __restrict__ W2, const float* __restrict__ b2) {
    __shared__ float s[DD];
    int n = blockIdx.x, tid = threadIdx.x;
    s[tid] = g_h[n * DD + tid] + g_agg[n * DD + tid];
    __syncthreads();
    float acc = b2[tid];
#pragma unroll
    for (int k = 0; k < DD; k += 4) {
        float4 sv = *(const float4*)&s[k];
        acc += sv.x * W2[(k + 0) * DD + tid];
        acc += sv.y * W2[(k + 1) * DD + tid];
        acc += sv.z * W2[(k + 2) * DD + tid];
        acc += sv.w * W2[(k + 3) * DD + tid];
    }
    g_no[n * DD + tid] = fmaxf(acc, 0.0f);
}

__global__ void k_edge_x(const int* __restrict__ eidx, const float* __restrict__ Wc1,
                         const float* __restrict__ bc1) {
    __shared__ float s[8][DD];
    int e0 = blockIdx.x * 8, tid = threadIdx.x;
    for (int idx = tid; idx < 8 * DD; idx += 256) {
        int e = idx >> 6, k = idx & 63;
        int ge = e0 + e;
        int sN = eidx[ge], dN = eidx[EE + ge];
        s[e][k] = g_no[sN * DD + k] + g_no[dN * DD + k];
    }
    __syncthreads();
    for (int jj = 0; jj < 3; jj++) {
        int j = jj * 256 + tid;
        float acc[8];
        float bv = bc1[j];
#pragma unroll
        for (int e = 0; e < 8; e++) acc[e] = bv;
        for (int k = 0; k < DD; k += 4) {
            float w0 = Wc1[(k + 0) * HH + j];
            float w1 = Wc1[(k + 1) * HH + j];
            float w2 = Wc1[(k + 2) * HH + j];
            float w3 = Wc1[(k + 3) * HH + j];
#pragma unroll
            for (int e = 0; e < 8; e++) {
                float4 sv = *(const float4*)&s[e][k];
                acc[e] += sv.x * w0 + sv.y * w1 + sv.z * w2 + sv.w * w3;
            }
        }
#pragma unroll
        for (int e = 0; e < 8; e++) g_x[(size_t)(e0 + e) * HH + j] = acc[e];
    }
}

// ---------------- LayerNorm over H=768 -> bf16 ----------------
__global__ void k_ln(const float* __restrict__ lng, const float* __restrict__ lnb) {
    __shared__ float red[256];
    int row = blockIdx.x, tid = threadIdx.x;
    float v[3];
#pragma unroll
    for (int i = 0; i < 3; i++) v[i] = g_x[(size_t)row * HH + tid + i * 256];
    red[tid] = v[0] + v[1] + v[2];
    __syncthreads();
    for (int s = 128; s > 0; s >>= 1) {
        if (tid < s) red[tid] += red[tid + s];
        __syncthreads();
    }
    float mu = red[0] / (float)HH;
    __syncthreads();
    float d2 = 0.0f;
#pragma unroll
    for (int i = 0; i < 3; i++) { float d = v[i] - mu; d2 += d * d; }
    red[tid] = d2;
    __syncthreads();
    for (int s = 128; s > 0; s >>= 1) {
        if (tid < s) red[tid] += red[tid + s];
        __syncthreads();
    }
    float inv = rsqrtf(red[0] / (float)HH + 1e-5f);
#pragma unroll
    for (int i = 0; i < 3; i++) {
        int j = tid + i * 256;
        g_xnb[(size_t)row * HH + j] =
            __float2bfloat16((v[i] - mu) * inv * lng[j] + lnb[j]);
    }
}

// ---------------- proj = hidden @ Wc2 + bc2 -> bf16 [E,64] ----------------
__global__ void k_proj(const float* __restrict__ Wc2, const float* __restrict__ bc2) {
    __shared__ float s[16][HH];
    int e0 = blockIdx.x * 16, tid = threadIdx.x;
    int d = tid & 63, eg = tid >> 6;
    for (int idx = tid; idx < 16 * HH / 4; idx += 256) {
        int e = idx / (HH / 4), q = idx % (HH / 4);
        *(float4*)&s[e][q * 4] = *(const float4*)&g_hidden[(size_t)(e0 + e) * HH + q * 4];
    }
    __syncthreads();
    float acc[4];
    float bv = bc2[d];
#pragma unroll
    for (int i = 0; i < 4; i++) acc[i] = bv;
    for (int k = 0; k < HH; k += 4) {
        float w0 = Wc2[(k + 0) * DD + d];
        float w1 = Wc2[(k + 1) * DD + d];
        float w2 = Wc2[(k + 2) * DD + d];
        float w3 = Wc2[(k + 3) * DD + d];
#pragma unroll
        for (int i = 0; i < 4; i++) {
            int e = eg * 4 + i;
            float4 sv = *(const float4*)&s[e][k];
            acc[i] += sv.x * w0 + sv.y * w1 + sv.z * w2 + sv.w * w3;
        }
    }
#pragma unroll
    for (int i = 0; i < 4; i++)
        g_projb[(size_t)(e0 + eg * 4 + i) * DD + d] = __float2bfloat16(acc[i]);
}

// ---------------- labels = (float)edge_tokens ----------------
__global__ void k_labels(const int* __restrict__ etok, float* __restrict__ out) {
    int i = blockIdx.x * 256 + threadIdx.x;
    if (i < EE * LL) out[i] = (float)etok[i];
}

// ---------------- launch ----------------
extern "C" void kernel_launch(void* const* d_in, const int* in_sizes, int n_in,
                              void* d_out, int out_size) {
    const int*   xtok = (const int*)d_in[0];
    const int*   etok = (const int*)d_in[1];
    const int*   eidx = (const int*)d_in[2];
    const float* emb  = (const float*)d_in[3];
    const float* W1   = (const float*)d_in[4];
    const float* b1   = (const float*)d_in[5];
    const float* We   = (const float*)d_in[6];
    const float* W2   = (const float*)d_in[7];
    const float* b2   = (const float*)d_in[8];
    const float* Wc1  = (const float*)d_in[9];
    const float* bc1  = (const float*)d_in[10];
    const float* lng  = (const float*)d_in[11];
    const float* lnb  = (const float*)d_in[12];
    const float* Wt1  = (const float*)d_in[13];
    const float* bt1  = (const float*)d_in[14];
    const float* Wt2  = (const float*)d_in[15];
    const float* bt2  = (const float*)d_in[16];
    const float* Wc2  = (const float*)d_in[17];
    const float* bc2  = (const float*)d_in[18];

    float* out = (float*)d_out;
    long long off = (long long)out_size - (long long)EE * VV;
    float* probs = out + (off > 0 ? off : 0);

    float *p_x, *p_hidden, *p_rowsum;
    __nv_bfloat16 *p_xnb, *p_hidb, *p_projb, *p_wt1t, *p_wt2t, *p_embb;
    cudaGetSymbolAddress((void**)&p_x, g_x);
    cudaGetSymbolAddress((void**)&p_hidden, g_hidden);
    cudaGetSymbolAddress((void**)&p_rowsum, g_rowsum);
    cudaGetSymbolAddress((void**)&p_xnb, g_xnb);
    cudaGetSymbolAddress((void**)&p_hidb, g_hidb);
    cudaGetSymbolAddress((void**)&p_projb, g_projb);
    cudaGetSymbolAddress((void**)&p_wt1t, g_wt1t);
    cudaGetSymbolAddress((void**)&p_wt2t, g_wt2t);
    cudaGetSymbolAddress((void**)&p_embb, g_embb);

    // prolog: zero + bf16 conversions/transposes
    k_zero<<<(NN * DD + 255) / 256, 256>>>();
    k_cvt<<<(VV * DD + 255) / 256, 256>>>(emb, p_embb, VV * DD);
    k_transpose<<<dim3(FF / 32, HH / 32), dim3(32, 8)>>>(Wt1, p_wt1t, HH, FF);
    k_transpose<<<dim3(HH / 32, FF / 32), dim3(32, 8)>>>(Wt2, p_wt2t, FF, HH);

    // GNN front-end
    k_node_h<<<NN, 64>>>(xtok, emb, W1, b1);
    k_edge_msg<<<EE, 64>>>(etok, emb, We, eidx);
    k_node_out<<<NN, 64>>>(W2, b2);
    k_edge_x<<<EE / 8, 256>>>(eidx, Wc1, bc1);
    k_ln<<<EE, 256>>>(lng, lnb);

    // FFN up: g_hidb = gelu(xn @ Wt1 + bt1)        [8192,3072] bf16
    k_mma_gemm<1><<<dim3(FF / 128, EE / 128), 256>>>(p_xnb, p_wt1t, bt1, nullptr,
                                                     p_hidb, nullptr, EE, FF, HH);
    // FFN down: g_hidden = hid @ Wt2 + bt2 + x     [8192,768] fp32
    k_mma_gemm<2><<<dim3(HH / 128, EE / 128), 256>>>(p_hidb, p_wt2t, bt2, p_x,
                                                     p_hidden, nullptr, EE, HH, FF);
    // proj (bf16)
    k_proj<<<EE / 16, 256>>>(Wc2, bc2);

    // LM head pass A: rowsum = sum_v exp(proj @ emb^T)
    k_mma_gemm<3><<<dim3(VV / 128, EE / 128), 256>>>(p_projb, p_embb, nullptr, nullptr,
                                                     nullptr, p_rowsum, EE, VV, DD);
    // LM head pass B: probs = exp(logit) / rowsum  (written directly to d_out)
    k_mma_gemm<4><<<dim3(VV / 128, EE / 128), 256>>>(p_projb, p_embb, nullptr, nullptr,
                                                     probs, p_rowsum, EE, VV, DD);

    if (off > 0) k_labels<<<(EE * LL + 255) / 256, 256>>>(etok, out);
}

// round 10
// speedup vs baseline: 5.0305x; 1.1665x over previous
#include <cuda_runtime.h>
#include <cuda_bf16.h>
#include <math.h>
#include <cstdint>

#define NN 4096
#define EE 8192
#define DD 64
#define LL 16
#define HH 768
#define FF 3072
#define VV 32000

#define SMS 80       // smem row stride bytes (64B data + 16B pad)
#define STG 10240    // one 128-row x BK=32 tile: 128*SMS
#define NL 5         // LM-head n-blocks per CTA

// ---------------- scratch (static device globals; no allocation) ----------------
__device__ float g_h[NN * DD];
__device__ float g_agg[NN * DD];
__device__ float g_no[NN * DD];
__device__ float g_x[(size_t)EE * HH];          // pre-LN activations (residual)
__device__ float g_hidden[(size_t)EE * HH];     // transformer output fp32
__device__ float g_rowsum[EE];                  // softmax denominators
__device__ __nv_bfloat16 g_xnb[(size_t)EE * HH];    // LN output bf16
__device__ __nv_bfloat16 g_hidb[(size_t)EE * FF];   // gelu output bf16
__device__ __nv_bfloat16 g_projb[(size_t)EE * DD];  // proj bf16
__device__ __nv_bfloat16 g_edgeb[(size_t)EE * DD];  // edge_emb bf16
__device__ __nv_bfloat16 g_wt1t[(size_t)FF * HH];   // Wt1^T bf16 [3072,768]
__device__ __nv_bfloat16 g_wt2t[(size_t)HH * FF];   // Wt2^T bf16 [768,3072]
__device__ __nv_bfloat16 g_wc1t[(size_t)HH * DD];   // Wc1^T bf16 [768,64]
__device__ __nv_bfloat16 g_embb[(size_t)VV * DD];   // emb bf16 [32000,64]

__device__ __forceinline__ float gelu_tanh(float x) {
    float x3 = x * x * x;
    float t = tanhf(0.7978845608028654f * (x + 0.044715f * x3));
    return 0.5f * x * (1.0f + t);
}

__device__ __forceinline__ uint32_t smem_u32(const void* p) {
    uint32_t a;
    asm("{ .reg .u64 t; cvta.to.shared.u64 t, %1; cvt.u32.u64 %0, t; }" : "=r"(a) : "l"(p));
    return a;
}

#define CP_ASYNC16(dst, src) \
    asm volatile("cp.async.cg.shared.global [%0], [%1], 16;" :: "r"(dst), "l"(src))
#define CP_COMMIT() asm volatile("cp.async.commit_group;" ::: "memory")
#define CP_WAIT0()  asm volatile("cp.async.wait_group 0;" ::: "memory")

#define LDSM_X4(r0, r1, r2, r3, ad) \
    asm volatile("ldmatrix.sync.aligned.m8n8.x4.shared.b16 {%0,%1,%2,%3}, [%4];" \
                 : "=r"(r0), "=r"(r1), "=r"(r2), "=r"(r3) : "r"(ad))
#define LDSM_X2(r0, r1, ad) \
    asm volatile("ldmatrix.sync.aligned.m8n8.x2.shared.b16 {%0,%1}, [%2];" \
                 : "=r"(r0), "=r"(r1) : "r"(ad))
#define MMA16816(acc, a, b) \
    asm volatile("mma.sync.aligned.m16n8k16.row.col.f32.bf16.bf16.f32 " \
                 "{%0,%1,%2,%3}, {%4,%5,%6,%7}, {%8,%9}, {%0,%1,%2,%3};" \
                 : "+f"((acc)[0]), "+f"((acc)[1]), "+f"((acc)[2]), "+f"((acc)[3]) \
                 : "r"((a)[0]), "r"((a)[1]), "r"((a)[2]), "r"((a)[3]), \
                   "r"((b)[0]), "r"((b)[1]))

// ================= cp.async pipelined mma GEMM: C = A[M,K] @ B[Nn,K]^T =================
// BM=BN=128, BK=32, 2-stage. 256 threads = 8 warps (2x4), warp tile 64x32.
// EPI: 0 = acc+bias -> fp32 C
//      1 = gelu(acc+bias) -> bf16 C
//      2 = acc+bias+R -> fp32 C
template <int EPI>
__global__ __launch_bounds__(256) void k_mma_gemm(
    const __nv_bfloat16* __restrict__ A, const __nv_bfloat16* __restrict__ B,
    const float* __restrict__ bias, const float* __restrict__ R,
    void* __restrict__ Cout, int M, int Nn, int K)
{
    __shared__ __align__(16) char smA[2 * STG];
    __shared__ __align__(16) char smB[2 * STG];

    const int t = threadIdx.x;
    const int l = t & 31, w = t >> 5;
    const int wm = w & 1, wn = w >> 1;
    const int m0 = blockIdx.y * 128, n0 = blockIdx.x * 128;

    int rowL[2], c4L[2];
#pragma unroll
    for (int i = 0; i < 2; i++) {
        int chunk = t * 2 + i;
        rowL[i] = chunk >> 2;
        c4L[i] = chunk & 3;
    }
    const uint32_t uA = smem_u32(smA), uB = smem_u32(smB);
    const int rA = wm * 64 + (l & 7) + ((l >> 3) & 1) * 8;
    const uint32_t aBase = uA + (uint32_t)rA * SMS + (uint32_t)(l >> 4) * 16;
    const int lB = l & 15;
    const uint32_t bBase = uB + (uint32_t)(wn * 32 + (lB & 7)) * SMS + (uint32_t)(lB >> 3) * 16;

    float acc[4][4][4] = {};
    const int nk = K >> 5;

    // prologue: issue tile 0 into stage 0
#pragma unroll
    for (int i = 0; i < 2; i++) {
        CP_ASYNC16(uA + rowL[i] * SMS + c4L[i] * 16,
                   A + (size_t)(m0 + rowL[i]) * K + c4L[i] * 8);
        CP_ASYNC16(uB + rowL[i] * SMS + c4L[i] * 16,
                   B + (size_t)(n0 + rowL[i]) * K + c4L[i] * 8);
    }
    CP_COMMIT();

    for (int it = 0; it < nk; it++) {
        CP_WAIT0();
        __syncthreads();
        if (it + 1 < nk) {
            int kt = (it + 1) * 32;
            uint32_t so = ((it + 1) & 1) * STG;
#pragma unroll
            for (int i = 0; i < 2; i++) {
                CP_ASYNC16(uA + so + rowL[i] * SMS + c4L[i] * 16,
                           A + (size_t)(m0 + rowL[i]) * K + kt + c4L[i] * 8);
                CP_ASYNC16(uB + so + rowL[i] * SMS + c4L[i] * 16,
                           B + (size_t)(n0 + rowL[i]) * K + kt + c4L[i] * 8);
            }
            CP_COMMIT();
        }
        const uint32_t so = (it & 1) * STG;
#pragma unroll
        for (int ks = 0; ks < 2; ks++) {
            uint32_t a[4][4], b[4][2];
#pragma unroll
            for (int i = 0; i < 4; i++)
                LDSM_X4(a[i][0], a[i][1], a[i][2], a[i][3],
                        aBase + so + (uint32_t)(i * 16) * SMS + ks * 32);
#pragma unroll
            for (int j = 0; j < 4; j++)
                LDSM_X2(b[j][0], b[j][1],
                        bBase + so + (uint32_t)(j * 8) * SMS + ks * 32);
#pragma unroll
            for (int i = 0; i < 4; i++)
#pragma unroll
                for (int j = 0; j < 4; j++) MMA16816(acc[i][j], a[i], b[j]);
        }
    }

    // ---------------- epilogue ----------------
    const int mw = m0 + wm * 64;
#pragma unroll
    for (int i = 0; i < 4; i++) {
        int rlo = mw + i * 16 + (l >> 2);
        int rhi = rlo + 8;
#pragma unroll
        for (int j = 0; j < 4; j++) {
            int col = n0 + wn * 32 + j * 8 + (l & 3) * 2;
            float b0 = bias[col], b1 = bias[col + 1];
            if (EPI == 1) {
                __nv_bfloat162 plo, phi;
                plo.x = __float2bfloat16(gelu_tanh(acc[i][j][0] + b0));
                plo.y = __float2bfloat16(gelu_tanh(acc[i][j][1] + b1));
                phi.x = __float2bfloat16(gelu_tanh(acc[i][j][2] + b0));
                phi.y = __float2bfloat16(gelu_tanh(acc[i][j][3] + b1));
                *(__nv_bfloat162*)((__nv_bfloat16*)Cout + (size_t)rlo * Nn + col) = plo;
                *(__nv_bfloat162*)((__nv_bfloat16*)Cout + (size_t)rhi * Nn + col) = phi;
            } else {
                float2 plo, phi;
                plo.x = acc[i][j][0] + b0;
                plo.y = acc[i][j][1] + b1;
                phi.x = acc[i][j][2] + b0;
                phi.y = acc[i][j][3] + b1;
                if (EPI == 2) {
                    const float* Rlo = R + (size_t)rlo * Nn + col;
                    const float* Rhi = R + (size_t)rhi * Nn + col;
                    plo.x += Rlo[0]; plo.y += Rlo[1];
                    phi.x += Rhi[0]; phi.y += Rhi[1];
                }
                *(float2*)((float*)Cout + (size_t)rlo * Nn + col) = plo;
                *(float2*)((float*)Cout + (size_t)rhi * Nn + col) = phi;
            }
        }
    }
}

// ================= LM head: logits = projb[E,64] @ embb[V,64]^T, fused softmax ======
// K=64 (A resident in smem), NL n-blocks of 128 per CTA, B cp.async double-buffered.
// EPI: 3 = rowsum[row] += sum_v exp(logit)      (register accumulation, 1 atomic/row)
//      4 = C = exp(logit) * (1/rowsum[row]) -> fp32
template <int EPI>
__global__ __launch_bounds__(256) void k_lmhead(
    const __nv_bfloat16* __restrict__ A, const __nv_bfloat16* __restrict__ B,
    float* __restrict__ Cout, float* __restrict__ rowsum)
{
    extern __shared__ __align__(16) char dsm[];   // [0,2*STG): A ; [2*STG,6*STG): B stages
    const int t = threadIdx.x;
    const int l = t & 31, w = t >> 5;
    const int wm = w & 1, wn = w >> 1;
    const int m0 = blockIdx.y * 128;
    const int nbase = blockIdx.x * (NL * 128);

    const uint32_t uA = smem_u32(dsm);
    const uint32_t uB = uA + 2 * STG;

    // A: 128x64 bf16, two BK=32 slices, direct load
#pragma unroll
    for (int s = 0; s < 2; s++)
#pragma unroll
        for (int i = 0; i < 2; i++) {
            int chunk = t * 2 + i, row = chunk >> 2, c4 = chunk & 3;
            uint4 v = *(const uint4*)(A + (size_t)(m0 + row) * DD + s * 32 + c4 * 8);
            *(uint4*)(dsm + s * STG + row * SMS + c4 * 16) = v;
        }

    // B issue: one n-block = 2 slices x 128 rows x 32 bf16; 4 chunks/thread
    int rowB[4], c4B[4], slB[4];
#pragma unroll
    for (int i = 0; i < 4; i++) {
        int chunk = t * 4 + i;
        slB[i] = chunk >> 9;
        int c = chunk & 511;
        rowB[i] = c >> 2;
        c4B[i] = c & 3;
    }
    {
#pragma unroll
        for (int i = 0; i < 4; i++)
            CP_ASYNC16(uB + slB[i] * STG + rowB[i] * SMS + c4B[i] * 16,
                       B + (size_t)(nbase + rowB[i]) * DD + slB[i] * 32 + c4B[i] * 8);
        CP_COMMIT();
    }

    const int rA = wm * 64 + (l & 7) + ((l >> 3) & 1) * 8;
    const uint32_t aBase = uA + (uint32_t)rA * SMS + (uint32_t)(l >> 4) * 16;
    const int lB2 = l & 15;
    const uint32_t bBase = uB + (uint32_t)(wn * 32 + (lB2 & 7)) * SMS + (uint32_t)(lB2 >> 3) * 16;

    // row base for this warp: m-tile + warp-row offset (wm*64) [R9 bug: wm*64 was missing]
    const int mrow = m0 + wm * 64;

    float inv[8], psum[8];
#pragma unroll
    for (int i = 0; i < 4; i++) {
        if (EPI == 4) {
            inv[i] = 1.0f / rowsum[mrow + i * 16 + (l >> 2)];
            inv[i + 4] = 1.0f / rowsum[mrow + i * 16 + (l >> 2) + 8];
        } else {
            psum[i] = 0.0f; psum[i + 4] = 0.0f;
        }
    }

    for (int nl = 0; nl < NL; nl++) {
        CP_WAIT0();
        __syncthreads();
        if (nl + 1 < NL) {
            uint32_t so = ((nl + 1) & 1) * (2 * STG);
            int n1 = nbase + (nl + 1) * 128;
#pragma unroll
            for (int i = 0; i < 4; i++)
                CP_ASYNC16(uB + so + slB[i] * STG + rowB[i] * SMS + c4B[i] * 16,
                           B + (size_t)(n1 + rowB[i]) * DD + slB[i] * 32 + c4B[i] * 8);
            CP_COMMIT();
        }
        const uint32_t bs = (nl & 1) * (2 * STG);
        float acc[4][4][4] = {};
#pragma unroll
        for (int s = 0; s < 2; s++)
#pragma unroll
            for (int ks = 0; ks < 2; ks++) {
                uint32_t a[4][4], b[4][2];
#pragma unroll
                for (int i = 0; i < 4; i++)
                    LDSM_X4(a[i][0], a[i][1], a[i][2], a[i][3],
                            aBase + s * STG + (uint32_t)(i * 16) * SMS + ks * 32);
#pragma unroll
                for (int j = 0; j < 4; j++)
                    LDSM_X2(b[j][0], b[j][1],
                            bBase + bs + s * STG + (uint32_t)(j * 8) * SMS + ks * 32);
#pragma unroll
                for (int i = 0; i < 4; i++)
#pragma unroll
                    for (int j = 0; j < 4; j++) MMA16816(acc[i][j], a[i], b[j]);
            }
        const int n0 = nbase + nl * 128;
#pragma unroll
        for (int i = 0; i < 4; i++) {
            if (EPI == 3) {
#pragma unroll
                for (int j = 0; j < 4; j++) {
                    psum[i]     += __expf(acc[i][j][0]) + __expf(acc[i][j][1]);
                    psum[i + 4] += __expf(acc[i][j][2]) + __expf(acc[i][j][3]);
                }
            } else {
                int rlo = mrow + i * 16 + (l >> 2);
                int rhi = rlo + 8;
#pragma unroll
                for (int j = 0; j < 4; j++) {
                    int col = n0 + wn * 32 + j * 8 + (l & 3) * 2;
                    float2 plo, phi;
                    plo.x = __expf(acc[i][j][0]) * inv[i];
                    plo.y = __expf(acc[i][j][1]) * inv[i];
                    phi.x = __expf(acc[i][j][2]) * inv[i + 4];
                    phi.y = __expf(acc[i][j][3]) * inv[i + 4];
                    *(float2*)(Cout + (size_t)rlo * VV + col) = plo;
                    *(float2*)(Cout + (size_t)rhi * VV + col) = phi;
                }
            }
        }
    }
    if (EPI == 3) {
#pragma unroll
        for (int i = 0; i < 4; i++) {
            float slo = psum[i], shi = psum[i + 4];
            slo += __shfl_xor_sync(0xFFFFFFFF, slo, 1);
            slo += __shfl_xor_sync(0xFFFFFFFF, slo, 2);
            shi += __shfl_xor_sync(0xFFFFFFFF, shi, 1);
            shi += __shfl_xor_sync(0xFFFFFFFF, shi, 2);
            if ((l & 3) == 0) {
                atomicAdd(&rowsum[mrow + i * 16 + (l >> 2)], slo);
                atomicAdd(&rowsum[mrow + i * 16 + (l >> 2) + 8], shi);
            }
        }
    }
}

// ---------------- conversion / transpose prolog ----------------
__global__ void k_transpose(const float* __restrict__ in, __nv_bfloat16* __restrict__ out,
                            int Rr, int Cc) {
    __shared__ float tbuf[32][33];
    int r0 = blockIdx.y * 32, c0 = blockIdx.x * 32;
    int x = threadIdx.x, y = threadIdx.y;
#pragma unroll
    for (int i = 0; i < 32; i += 8) tbuf[y + i][x] = in[(size_t)(r0 + y + i) * Cc + c0 + x];
    __syncthreads();
#pragma unroll
    for (int i = 0; i < 32; i += 8)
        out[(size_t)(c0 + y + i) * Rr + r0 + x] = __float2bfloat16(tbuf[x][y + i]);
}
__global__ void k_cvt(const float* __restrict__ in, __nv_bfloat16* __restrict__ out, int n) {
    int i = blockIdx.x * 256 + threadIdx.x;
    if (i < n) out[i] = __float2bfloat16(in[i]);
}
__global__ void k_zero() {
    int i = blockIdx.x * 256 + threadIdx.x;
    if (i < NN * DD) g_agg[i] = 0.0f;
    if (i < EE) g_rowsum[i] = 0.0f;
}

// ---------------- GNN front-end ----------------
__global__ void k_node_h(const int* __restrict__ xtok, const float* __restrict__ emb,
                         const float* __restrict__ W1, const float* __restrict__ b1) {
    __shared__ float s[LL * DD];
    int n = blockIdx.x, tid = threadIdx.x;
#pragma unroll
    for (int j = 0; j < LL; j++) {
        int tok = xtok[n * LL + j];
        s[j * DD + tid] = emb[(size_t)tok * DD + tid];
    }
    __syncthreads();
    float acc = b1[tid];
#pragma unroll 8
    for (int k = 0; k < LL * DD; k += 4) {
        float4 sv = *(const float4*)&s[k];
        acc += sv.x * W1[(k + 0) * DD + tid];
        acc += sv.y * W1[(k + 1) * DD + tid];
        acc += sv.z * W1[(k + 2) * DD + tid];
        acc += sv.w * W1[(k + 3) * DD + tid];
    }
    g_h[n * DD + tid] = fmaxf(acc, 0.0f);
}

__global__ void k_edge_msg(const int* __restrict__ etok, const float* __restrict__ emb,
                           const float* __restrict__ We, const int* __restrict__ eidx) {
    __shared__ float s[LL * DD];
    int e = blockIdx.x, tid = threadIdx.x;
#pragma unroll
    for (int j = 0; j < LL; j++) {
        int tok = etok[e * LL + j];
        s[j * DD + tid] = emb[(size_t)tok * DD + tid];
    }
    __syncthreads();
    float acc = 0.0f;
#pragma unroll 8
    for (int k = 0; k < LL * DD; k += 4) {
        float4 sv = *(const float4*)&s[k];
        acc += sv.x * We[(k + 0) * DD + tid];
        acc += sv.y * We[(k + 1) * DD + tid];
        acc += sv.z * We[(k + 2) * DD + tid];
        acc += sv.w * We[(k + 3) * DD + tid];
    }
    int src = eidx[e], dst = eidx[EE + e];
    float m = acc + g_h[src * DD + tid];
    atomicAdd(&g_agg[dst * DD + tid], m);
}

__global__ void k_node_out(const float* __restrict__ W2, const float* __restrict__ b2) {
    __shared__ float s[DD];
    int n = blockIdx.x, tid = threadIdx.x;
    s[tid] = g_h[n * DD + tid] + g_agg[n * DD + tid];
    __syncthreads();
    float acc = b2[tid];
#pragma unroll
    for (int k = 0; k < DD; k += 4) {
        float4 sv = *(const float4*)&s[k];
        acc += sv.x * W2[(k + 0) * DD + tid];
        acc += sv.y * W2[(k + 1) * DD + tid];
        acc += sv.z * W2[(k + 2) * DD + tid];
        acc += sv.w * W2[(k + 3) * DD + tid];
    }
    g_no[n * DD + tid] = fmaxf(acc, 0.0f);
}

// edge_emb (bf16) = node_out[src] + node_out[dst]
__global__ void k_edge_gather(const int* __restrict__ eidx) {
    int i = blockIdx.x * 256 + threadIdx.x;
    if (i < EE * DD) {
        int e = i >> 6, d = i & 63;
        int s = eidx[e], dn = eidx[EE + e];
        g_edgeb[i] = __float2bfloat16(g_no[s * DD + d] + g_no[dn * DD + d]);
    }
}

// ---------------- LayerNorm over H=768 -> bf16 ----------------
__global__ void k_ln(const float* __restrict__ lng, const float* __restrict__ lnb) {
    __shared__ float red[256];
    int row = blockIdx.x, tid = threadIdx.x;
    float v[3];
#pragma unroll
    for (int i = 0; i < 3; i++) v[i] = g_x[(size_t)row * HH + tid + i * 256];
    red[tid] = v[0] + v[1] + v[2];
    __syncthreads();
    for (int s = 128; s > 0; s >>= 1) {
        if (tid < s) red[tid] += red[tid + s];
        __syncthreads();
    }
    float mu = red[0] / (float)HH;
    __syncthreads();
    float d2 = 0.0f;
#pragma unroll
    for (int i = 0; i < 3; i++) { float d = v[i] - mu; d2 += d * d; }
    red[tid] = d2;
    __syncthreads();
    for (int s = 128; s > 0; s >>= 1) {
        if (tid < s) red[tid] += red[tid + s];
        __syncthreads();
    }
    float inv = rsqrtf(red[0] / (float)HH + 1e-5f);
#pragma unroll
    for (int i = 0; i < 3; i++) {
        int j = tid + i * 256;
        g_xnb[(size_t)row * HH + j] =
            __float2bfloat16((v[i] - mu) * inv * lng[j] + lnb[j]);
    }
}

// ---------------- proj = hidden @ Wc2 + bc2 -> bf16 [E,64] ----------------
__global__ void k_proj(const float* __restrict__ Wc2, const float* __restrict__ bc2) {
    __shared__ float s[16][HH];
    int e0 = blockIdx.x * 16, tid = threadIdx.x;
    int d = tid & 63, eg = tid >> 6;
    for (int idx = tid; idx < 16 * HH / 4; idx += 256) {
        int e = idx / (HH / 4), q = idx % (HH / 4);
        *(float4*)&s[e][q * 4] = *(const float4*)&g_hidden[(size_t)(e0 + e) * HH + q * 4];
    }
    __syncthreads();
    float acc[4];
    float bv = bc2[d];
#pragma unroll
    for (int i = 0; i < 4; i++) acc[i] = bv;
    for (int k = 0; k < HH; k += 4) {
        float w0 = Wc2[(k + 0) * DD + d];
        float w1 = Wc2[(k + 1) * DD + d];
        float w2 = Wc2[(k + 2) * DD + d];
        float w3 = Wc2[(k + 3) * DD + d];
#pragma unroll
        for (int i = 0; i < 4; i++) {
            int e = eg * 4 + i;
            float4 sv = *(const float4*)&s[e][k];
            acc[i] += sv.x * w0 + sv.y * w1 + sv.z * w2 + sv.w * w3;
        }
    }
#pragma unroll
    for (int i = 0; i < 4; i++)
        g_projb[(size_t)(e0 + eg * 4 + i) * DD + d] = __float2bfloat16(acc[i]);
}

// ---------------- labels = (float)edge_tokens ----------------
__global__ void k_labels(const int* __restrict__ etok, float* __restrict__ out) {
    int i = blockIdx.x * 256 + threadIdx.x;
    if (i < EE * LL) out[i] = (float)etok[i];
}

// ---------------- launch ----------------
extern "C" void kernel_launch(void* const* d_in, const int* in_sizes, int n_in,
                              void* d_out, int out_size) {
    const int*   xtok = (const int*)d_in[0];
    const int*   etok = (const int*)d_in[1];
    const int*   eidx = (const int*)d_in[2];
    const float* emb  = (const float*)d_in[3];
    const float* W1   = (const float*)d_in[4];
    const float* b1   = (const float*)d_in[5];
    const float* We   = (const float*)d_in[6];
    const float* W2   = (const float*)d_in[7];
    const float* b2   = (const float*)d_in[8];
    const float* Wc1  = (const float*)d_in[9];
    const float* bc1  = (const float*)d_in[10];
    const float* lng  = (const float*)d_in[11];
    const float* lnb  = (const float*)d_in[12];
    const float* Wt1  = (const float*)d_in[13];
    const float* bt1  = (const float*)d_in[14];
    const float* Wt2  = (const float*)d_in[15];
    const float* bt2  = (const float*)d_in[16];
    const float* Wc2  = (const float*)d_in[17];
    const float* bc2  = (const float*)d_in[18];

    float* out = (float*)d_out;
    long long off = (long long)out_size - (long long)EE * VV;
    float* probs = out + (off > 0 ? off : 0);

    float *p_x, *p_hidden, *p_rowsum;
    __nv_bfloat16 *p_xnb, *p_hidb, *p_projb, *p_edgeb, *p_wt1t, *p_wt2t, *p_wc1t, *p_embb;
    cudaGetSymbolAddress((void**)&p_x, g_x);
    cudaGetSymbolAddress((void**)&p_hidden, g_hidden);
    cudaGetSymbolAddress((void**)&p_rowsum, g_rowsum);
    cudaGetSymbolAddress((void**)&p_xnb, g_xnb);
    cudaGetSymbolAddress((void**)&p_hidb, g_hidb);
    cudaGetSymbolAddress((void**)&p_projb, g_projb);
    cudaGetSymbolAddress((void**)&p_edgeb, g_edgeb);
    cudaGetSymbolAddress((void**)&p_wt1t, g_wt1t);
    cudaGetSymbolAddress((void**)&p_wt2t, g_wt2t);
    cudaGetSymbolAddress((void**)&p_wc1t, g_wc1t);
    cudaGetSymbolAddress((void**)&p_embb, g_embb);

    cudaFuncSetAttribute((const void*)k_lmhead<3>,
                         cudaFuncAttributeMaxDynamicSharedMemorySize, 6 * STG);
    cudaFuncSetAttribute((const void*)k_lmhead<4>,
                         cudaFuncAttributeMaxDynamicSharedMemorySize, 6 * STG);

    // prolog: zero + bf16 conversions/transposes
    k_zero<<<(NN * DD + 255) / 256, 256>>>();
    k_cvt<<<(VV * DD + 255) / 256, 256>>>(emb, p_embb, VV * DD);
    k_transpose<<<dim3(FF / 32, HH / 32), dim3(32, 8)>>>(Wt1, p_wt1t, HH, FF);
    k_transpose<<<dim3(HH / 32, FF / 32), dim3(32, 8)>>>(Wt2, p_wt2t, FF, HH);
    k_transpose<<<dim3(HH / 32, DD / 32), dim3(32, 8)>>>(Wc1, p_wc1t, DD, HH);

    // GNN front-end
    k_node_h<<<NN, 64>>>(xtok, emb, W1, b1);
    k_edge_msg<<<EE, 64>>>(etok, emb, We, eidx);
    k_node_out<<<NN, 64>>>(W2, b2);
    k_edge_gather<<<(EE * DD + 255) / 256, 256>>>(eidx);

    // x = edge_emb @ Wc1 + bc1   (tensor path, fp32 out)
    k_mma_gemm<0><<<dim3(HH / 128, EE / 128), 256>>>(p_edgeb, p_wc1t, bc1, nullptr,
                                                     p_x, EE, HH, DD);
    k_ln<<<EE, 256>>>(lng, lnb);

    // FFN up: g_hidb = gelu(xn @ Wt1 + bt1)
    k_mma_gemm<1><<<dim3(FF / 128, EE / 128), 256>>>(p_xnb, p_wt1t, bt1, nullptr,
                                                     p_hidb, EE, FF, HH);
    // FFN down: g_hidden = hid @ Wt2 + bt2 + x
    k_mma_gemm<2><<<dim3(HH / 128, EE / 128), 256>>>(p_hidb, p_wt2t, bt2, p_x,
                                                     p_hidden, EE, HH, FF);
    // proj (bf16)
    k_proj<<<EE / 16, 256>>>(Wc2, bc2);

    // LM head pass A: rowsum; pass B: probs straight into d_out
    k_lmhead<3><<<dim3(VV / 128 / NL, EE / 128), 256, 6 * STG>>>(p_projb, p_embb,
                                                                 nullptr, p_rowsum);
    k_lmhead<4><<<dim3(VV / 128 / NL, EE / 128), 256, 6 * STG>>>(p_projb, p_embb,
                                                                 probs, p_rowsum);

    if (off > 0) k_labels<<<(EE * LL + 255) / 256, 256>>>(etok, out);
}